// round 2
// baseline (speedup 1.0000x reference)
#include <cuda_runtime.h>

// ---------------------------------------------------------------------------
// 2-layer GRU, B=256, T=24, D=2, N=512, H=128.
// B*N = 131072 independent sequences sharing weights.
// Each CTA: 64 sequences (one b, 64 consecutive n), hidden state resident in
// SMEM across all 24 timesteps. Register-tiled fp32 GEMMs with the gate
// triple {g, 128+g, 256+g} owned by a single thread -> in-register epilogue.
// (Resubmission of R0 design: R1 failed on broker infra, no HW signal.)
// ---------------------------------------------------------------------------

namespace {
constexpr int Bb      = 256;
constexpr int Tt      = 24;
constexpr int Dd      = 2;
constexpr int Nn      = 512;
constexpr int Hh      = 128;
constexpr int G3      = 384;     // 3*H
constexpr int SEQ     = 64;      // sequences per CTA
constexpr int THREADS = 512;
constexpr int NTILES  = Nn / SEQ;    // 8
constexpr int CTAS    = Bb * NTILES; // 2048
constexpr int HT      = 68;          // padded seq-stride of hT tiles (bank-conflict pad)

// shared memory layout (float offsets)
constexpr int OFF_WS  = 0;                    // 32 x 384 weight staging chunk
constexpr int OFF_H0  = OFF_WS  + 32 * G3;    // hT0 [128][HT]
constexpr int OFF_H1  = OFF_H0  + Hh * HT;    // hT1 [128][HT]
constexpr int OFF_X   = OFF_H1  + Hh * HT;    // xs  [T][D][SEQ]
constexpr int OFF_WX0 = OFF_X   + Tt * Dd * SEQ; // Wx0 [2][384]
constexpr int OFF_BX0 = OFF_WX0 + Dd * G3;
constexpr int OFF_BH0 = OFF_BX0 + G3;
constexpr int OFF_BX1 = OFF_BH0 + G3;
constexpr int OFF_BH1 = OFF_BX1 + G3;
constexpr int SMEM_FLOATS = OFF_BH1 + G3;     // 35072 floats = 140288 bytes
}

__device__ __forceinline__ float sigm_f(float x) {
    // 1/(1+e^-x); robust at extremes (e^-x -> inf gives 0, -> 0 gives 1)
    return __fdividef(1.0f, 1.0f + __expf(-x));
}
__device__ __forceinline__ float tanh_f(float x) {
    // 1 - 2/(e^{2x}+1); robust: e->inf => 1, e->0 => -1
    float e = __expf(2.0f * x);
    return 1.0f - __fdividef(2.0f, e + 1.0f);
}

__global__ void __launch_bounds__(THREADS)
gru_fused_kernel(const float* __restrict__ x,
                 const float* __restrict__ Wx0, const float* __restrict__ Wh0,
                 const float* __restrict__ bx0, const float* __restrict__ bh0,
                 const float* __restrict__ Wx1, const float* __restrict__ Wh1,
                 const float* __restrict__ bx1, const float* __restrict__ bh1,
                 float* __restrict__ out)
{
    extern __shared__ float sm[];
    float* Ws   = sm + OFF_WS;
    float* h0s  = sm + OFF_H0;
    float* h1s  = sm + OFF_H1;
    float* xs   = sm + OFF_X;
    float* wx0s = sm + OFF_WX0;
    float* vbx0 = sm + OFF_BX0;
    float* vbh0 = sm + OFF_BH0;
    float* vbx1 = sm + OFF_BX1;
    float* vbh1 = sm + OFF_BH1;

    const int tid = threadIdx.x;
    const int b   = blockIdx.x >> 3;          // NTILES = 8
    const int n0  = (blockIdx.x & 7) * SEQ;
    const int s0  = (tid & 15) * 4;           // this thread's 4 sequences
    const int g0  = (tid >> 4) * 4;           // this thread's 4 hidden-gate cols

    // ---- stage per-CTA constants ----
    for (int i = tid; i < Tt * Dd * SEQ; i += THREADS) {
        int t = i >> 7;            // / (D*SEQ) = 128
        int d = (i >> 6) & 1;
        int s = i & 63;
        xs[i] = x[((b * Tt + t) * Dd + d) * Nn + n0 + s];
    }
    for (int i = tid; i < Dd * G3; i += THREADS) wx0s[i] = Wx0[i];
    for (int i = tid; i < G3; i += THREADS) {
        vbx0[i] = bx0[i]; vbh0[i] = bh0[i];
        vbx1[i] = bx1[i]; vbh1[i] = bh1[i];
    }
    for (int i = tid; i < Hh * HT; i += THREADS) { h0s[i] = 0.0f; h1s[i] = 0.0f; }

    #pragma unroll 1
    for (int t = 0; t < Tt; t++) {
        // ================= layer 0: acc = h0 @ Wh0 =================
        float acc[4][12];
        #pragma unroll
        for (int s = 0; s < 4; s++)
            #pragma unroll
            for (int j = 0; j < 12; j++) acc[s][j] = 0.0f;

        #pragma unroll 1
        for (int kc = 0; kc < 4; kc++) {
            __syncthreads();   // protect Ws from previous consumers
            {
                const float4* src = reinterpret_cast<const float4*>(Wh0 + kc * 32 * G3);
                float4* dst = reinterpret_cast<float4*>(Ws);
                #pragma unroll
                for (int i = 0; i < (32 * G3 / 4) / THREADS; i++)  // 6
                    dst[tid + i * THREADS] = src[tid + i * THREADS];
            }
            __syncthreads();
            #pragma unroll 4
            for (int kk = 0; kk < 32; kk++) {
                const int k = kc * 32 + kk;
                float4 hv = *reinterpret_cast<const float4*>(&h0s[k * HT + s0]);
                float4 wr = *reinterpret_cast<const float4*>(&Ws[kk * G3 + g0]);
                float4 wz = *reinterpret_cast<const float4*>(&Ws[kk * G3 + 128 + g0]);
                float4 wn = *reinterpret_cast<const float4*>(&Ws[kk * G3 + 256 + g0]);
                const float hh[4]  = {hv.x, hv.y, hv.z, hv.w};
                const float wrv[4] = {wr.x, wr.y, wr.z, wr.w};
                const float wzv[4] = {wz.x, wz.y, wz.z, wz.w};
                const float wnv[4] = {wn.x, wn.y, wn.z, wn.w};
                #pragma unroll
                for (int s = 0; s < 4; s++) {
                    #pragma unroll
                    for (int j = 0; j < 4; j++) {
                        acc[s][j]     = fmaf(hh[s], wrv[j], acc[s][j]);
                        acc[s][4 + j] = fmaf(hh[s], wzv[j], acc[s][4 + j]);
                        acc[s][8 + j] = fmaf(hh[s], wnv[j], acc[s][8 + j]);
                    }
                }
            }
        }
        __syncthreads();   // all GEMM reads of h0s done before epilogue writes

        // ---- layer-0 gate epilogue (in-register) ----
        #pragma unroll
        for (int s = 0; s < 4; s++) {
            const int seq = s0 + s;
            const float x0v = xs[(t * Dd + 0) * SEQ + seq];
            const float x1v = xs[(t * Dd + 1) * SEQ + seq];
            #pragma unroll
            for (int j = 0; j < 4; j++) {
                const int g = g0 + j;
                float gir = fmaf(x1v, wx0s[G3 + g],       fmaf(x0v, wx0s[g],       vbx0[g]));
                float giz = fmaf(x1v, wx0s[G3 + 128 + g], fmaf(x0v, wx0s[128 + g], vbx0[128 + g]));
                float gin = fmaf(x1v, wx0s[G3 + 256 + g], fmaf(x0v, wx0s[256 + g], vbx0[256 + g]));
                float r  = sigm_f(acc[s][j]     + vbh0[g]       + gir);
                float z  = sigm_f(acc[s][4 + j] + vbh0[128 + g] + giz);
                float hn = acc[s][8 + j] + vbh0[256 + g];
                float nn = tanh_f(gin + r * hn);
                float ho = h0s[g * HT + seq];
                h0s[g * HT + seq] = (1.0f - z) * nn + z * ho;
            }
        }
        __syncthreads();   // new h0 visible to layer-1 GEMM

        // ================= layer 1 =================
        // slots: [0..3]=r, [4..7]=z, [8..11]=i_n (x-path), [12..15]=h_n (h-path)
        float a1[4][16];
        #pragma unroll
        for (int s = 0; s < 4; s++)
            #pragma unroll
            for (int j = 0; j < 16; j++) a1[s][j] = 0.0f;

        // x-path: h0_new @ Wx1
        #pragma unroll 1
        for (int kc = 0; kc < 4; kc++) {
            __syncthreads();
            {
                const float4* src = reinterpret_cast<const float4*>(Wx1 + kc * 32 * G3);
                float4* dst = reinterpret_cast<float4*>(Ws);
                #pragma unroll
                for (int i = 0; i < (32 * G3 / 4) / THREADS; i++)
                    dst[tid + i * THREADS] = src[tid + i * THREADS];
            }
            __syncthreads();
            #pragma unroll 4
            for (int kk = 0; kk < 32; kk++) {
                const int k = kc * 32 + kk;
                float4 hv = *reinterpret_cast<const float4*>(&h0s[k * HT + s0]);
                float4 wr = *reinterpret_cast<const float4*>(&Ws[kk * G3 + g0]);
                float4 wz = *reinterpret_cast<const float4*>(&Ws[kk * G3 + 128 + g0]);
                float4 wn = *reinterpret_cast<const float4*>(&Ws[kk * G3 + 256 + g0]);
                const float hh[4]  = {hv.x, hv.y, hv.z, hv.w};
                const float wrv[4] = {wr.x, wr.y, wr.z, wr.w};
                const float wzv[4] = {wz.x, wz.y, wz.z, wz.w};
                const float wnv[4] = {wn.x, wn.y, wn.z, wn.w};
                #pragma unroll
                for (int s = 0; s < 4; s++) {
                    #pragma unroll
                    for (int j = 0; j < 4; j++) {
                        a1[s][j]      = fmaf(hh[s], wrv[j], a1[s][j]);
                        a1[s][4 + j]  = fmaf(hh[s], wzv[j], a1[s][4 + j]);
                        a1[s][8 + j]  = fmaf(hh[s], wnv[j], a1[s][8 + j]);
                    }
                }
            }
        }
        // h-path: h1 @ Wh1
        #pragma unroll 1
        for (int kc = 0; kc < 4; kc++) {
            __syncthreads();
            {
                const float4* src = reinterpret_cast<const float4*>(Wh1 + kc * 32 * G3);
                float4* dst = reinterpret_cast<float4*>(Ws);
                #pragma unroll
                for (int i = 0; i < (32 * G3 / 4) / THREADS; i++)
                    dst[tid + i * THREADS] = src[tid + i * THREADS];
            }
            __syncthreads();
            #pragma unroll 4
            for (int kk = 0; kk < 32; kk++) {
                const int k = kc * 32 + kk;
                float4 hv = *reinterpret_cast<const float4*>(&h1s[k * HT + s0]);
                float4 wr = *reinterpret_cast<const float4*>(&Ws[kk * G3 + g0]);
                float4 wz = *reinterpret_cast<const float4*>(&Ws[kk * G3 + 128 + g0]);
                float4 wn = *reinterpret_cast<const float4*>(&Ws[kk * G3 + 256 + g0]);
                const float hh[4]  = {hv.x, hv.y, hv.z, hv.w};
                const float wrv[4] = {wr.x, wr.y, wr.z, wr.w};
                const float wzv[4] = {wz.x, wz.y, wz.z, wz.w};
                const float wnv[4] = {wn.x, wn.y, wn.z, wn.w};
                #pragma unroll
                for (int s = 0; s < 4; s++) {
                    #pragma unroll
                    for (int j = 0; j < 4; j++) {
                        a1[s][j]      = fmaf(hh[s], wrv[j], a1[s][j]);
                        a1[s][4 + j]  = fmaf(hh[s], wzv[j], a1[s][4 + j]);
                        a1[s][12 + j] = fmaf(hh[s], wnv[j], a1[s][12 + j]);
                    }
                }
            }
        }
        __syncthreads();   // all GEMM reads of h1s done before epilogue writes

        // ---- layer-1 gate epilogue ----
        #pragma unroll
        for (int s = 0; s < 4; s++) {
            const int seq = s0 + s;
            #pragma unroll
            for (int j = 0; j < 4; j++) {
                const int g = g0 + j;
                float r   = sigm_f(a1[s][j]     + vbx1[g]       + vbh1[g]);
                float z   = sigm_f(a1[s][4 + j] + vbx1[128 + g] + vbh1[128 + g]);
                float in_ = a1[s][8 + j]  + vbx1[256 + g];
                float hn  = a1[s][12 + j] + vbh1[256 + g];
                float nn  = tanh_f(in_ + r * hn);
                float ho  = h1s[g * HT + seq];
                h1s[g * HT + seq] = (1.0f - z) * nn + z * ho;
            }
        }
        __syncthreads();
    }

    // ---- write final hidden states: out[2][B][H][N] ----
    for (int i = tid; i < 2 * Hh * SEQ; i += THREADS) {
        int l   = i >> 13;          // / (H*SEQ) = 8192
        int rem = i & 8191;
        int g   = rem >> 6;
        int s   = rem & 63;
        float v = (l ? h1s : h0s)[g * HT + s];
        out[((l * Bb + b) * Hh + g) * Nn + n0 + s] = v;
    }
}

extern "C" void kernel_launch(void* const* d_in, const int* in_sizes, int n_in,
                              void* d_out, int out_size) {
    (void)in_sizes; (void)n_in; (void)out_size;
    const float* x   = (const float*)d_in[0];
    const float* Wx0 = (const float*)d_in[1];
    const float* Wh0 = (const float*)d_in[2];
    const float* bx0 = (const float*)d_in[3];
    const float* bh0 = (const float*)d_in[4];
    const float* Wx1 = (const float*)d_in[5];
    const float* Wh1 = (const float*)d_in[6];
    const float* bx1 = (const float*)d_in[7];
    const float* bh1 = (const float*)d_in[8];
    float* out = (float*)d_out;

    const size_t smem_bytes = SMEM_FLOATS * sizeof(float);  // 140288
    cudaFuncSetAttribute(gru_fused_kernel,
                         cudaFuncAttributeMaxDynamicSharedMemorySize,
                         (int)smem_bytes);

    gru_fused_kernel<<<CTAS, THREADS, smem_bytes>>>(
        x, Wx0, Wh0, bx0, bh0, Wx1, Wh1, bx1, bh1, out);
}

// round 3
// speedup vs baseline: 1.0011x; 1.0011x over previous
#include <cuda_runtime.h>

// ---------------------------------------------------------------------------
// 2-layer GRU, B=256, T=24, D=2, N=512, H=128.
// B*N = 131072 independent sequences sharing weights.
// Each CTA: 64 sequences (one b, 64 consecutive n), hidden state resident in
// SMEM across all 24 timesteps. Register-tiled fp32 GEMMs with the gate
// triple {g, 128+g, 256+g} owned by a single thread -> in-register epilogue.
// (Resubmission of R0 design: R1 failed on broker infra, no HW signal.)
// ---------------------------------------------------------------------------

namespace {
constexpr int Bb      = 256;
constexpr int Tt      = 24;
constexpr int Dd      = 2;
constexpr int Nn      = 512;
constexpr int Hh      = 128;
constexpr int G3      = 384;     // 3*H
constexpr int SEQ     = 64;      // sequences per CTA
constexpr int THREADS = 512;
constexpr int NTILES  = Nn / SEQ;    // 8
constexpr int CTAS    = Bb * NTILES; // 2048
constexpr int HT      = 68;          // padded seq-stride of hT tiles (bank-conflict pad)

// shared memory layout (float offsets)
constexpr int OFF_WS  = 0;                    // 32 x 384 weight staging chunk
constexpr int OFF_H0  = OFF_WS  + 32 * G3;    // hT0 [128][HT]
constexpr int OFF_H1  = OFF_H0  + Hh * HT;    // hT1 [128][HT]
constexpr int OFF_X   = OFF_H1  + Hh * HT;    // xs  [T][D][SEQ]
constexpr int OFF_WX0 = OFF_X   + Tt * Dd * SEQ; // Wx0 [2][384]
constexpr int OFF_BX0 = OFF_WX0 + Dd * G3;
constexpr int OFF_BH0 = OFF_BX0 + G3;
constexpr int OFF_BX1 = OFF_BH0 + G3;
constexpr int OFF_BH1 = OFF_BX1 + G3;
constexpr int SMEM_FLOATS = OFF_BH1 + G3;     // 35072 floats = 140288 bytes
}

__device__ __forceinline__ float sigm_f(float x) {
    // 1/(1+e^-x); robust at extremes (e^-x -> inf gives 0, -> 0 gives 1)
    return __fdividef(1.0f, 1.0f + __expf(-x));
}
__device__ __forceinline__ float tanh_f(float x) {
    // 1 - 2/(e^{2x}+1); robust: e->inf => 1, e->0 => -1
    float e = __expf(2.0f * x);
    return 1.0f - __fdividef(2.0f, e + 1.0f);
}

__global__ void __launch_bounds__(THREADS)
gru_fused_kernel(const float* __restrict__ x,
                 const float* __restrict__ Wx0, const float* __restrict__ Wh0,
                 const float* __restrict__ bx0, const float* __restrict__ bh0,
                 const float* __restrict__ Wx1, const float* __restrict__ Wh1,
                 const float* __restrict__ bx1, const float* __restrict__ bh1,
                 float* __restrict__ out)
{
    extern __shared__ float sm[];
    float* Ws   = sm + OFF_WS;
    float* h0s  = sm + OFF_H0;
    float* h1s  = sm + OFF_H1;
    float* xs   = sm + OFF_X;
    float* wx0s = sm + OFF_WX0;
    float* vbx0 = sm + OFF_BX0;
    float* vbh0 = sm + OFF_BH0;
    float* vbx1 = sm + OFF_BX1;
    float* vbh1 = sm + OFF_BH1;

    const int tid = threadIdx.x;
    const int b   = blockIdx.x >> 3;          // NTILES = 8
    const int n0  = (blockIdx.x & 7) * SEQ;
    const int s0  = (tid & 15) * 4;           // this thread's 4 sequences
    const int g0  = (tid >> 4) * 4;           // this thread's 4 hidden-gate cols

    // ---- stage per-CTA constants ----
    for (int i = tid; i < Tt * Dd * SEQ; i += THREADS) {
        int t = i >> 7;            // / (D*SEQ) = 128
        int d = (i >> 6) & 1;
        int s = i & 63;
        xs[i] = x[((b * Tt + t) * Dd + d) * Nn + n0 + s];
    }
    for (int i = tid; i < Dd * G3; i += THREADS) wx0s[i] = Wx0[i];
    for (int i = tid; i < G3; i += THREADS) {
        vbx0[i] = bx0[i]; vbh0[i] = bh0[i];
        vbx1[i] = bx1[i]; vbh1[i] = bh1[i];
    }
    for (int i = tid; i < Hh * HT; i += THREADS) { h0s[i] = 0.0f; h1s[i] = 0.0f; }

    #pragma unroll 1
    for (int t = 0; t < Tt; t++) {
        // ================= layer 0: acc = h0 @ Wh0 =================
        float acc[4][12];
        #pragma unroll
        for (int s = 0; s < 4; s++)
            #pragma unroll
            for (int j = 0; j < 12; j++) acc[s][j] = 0.0f;

        #pragma unroll 1
        for (int kc = 0; kc < 4; kc++) {
            __syncthreads();   // protect Ws from previous consumers
            {
                const float4* src = reinterpret_cast<const float4*>(Wh0 + kc * 32 * G3);
                float4* dst = reinterpret_cast<float4*>(Ws);
                #pragma unroll
                for (int i = 0; i < (32 * G3 / 4) / THREADS; i++)  // 6
                    dst[tid + i * THREADS] = src[tid + i * THREADS];
            }
            __syncthreads();
            #pragma unroll 4
            for (int kk = 0; kk < 32; kk++) {
                const int k = kc * 32 + kk;
                float4 hv = *reinterpret_cast<const float4*>(&h0s[k * HT + s0]);
                float4 wr = *reinterpret_cast<const float4*>(&Ws[kk * G3 + g0]);
                float4 wz = *reinterpret_cast<const float4*>(&Ws[kk * G3 + 128 + g0]);
                float4 wn = *reinterpret_cast<const float4*>(&Ws[kk * G3 + 256 + g0]);
                const float hh[4]  = {hv.x, hv.y, hv.z, hv.w};
                const float wrv[4] = {wr.x, wr.y, wr.z, wr.w};
                const float wzv[4] = {wz.x, wz.y, wz.z, wz.w};
                const float wnv[4] = {wn.x, wn.y, wn.z, wn.w};
                #pragma unroll
                for (int s = 0; s < 4; s++) {
                    #pragma unroll
                    for (int j = 0; j < 4; j++) {
                        acc[s][j]     = fmaf(hh[s], wrv[j], acc[s][j]);
                        acc[s][4 + j] = fmaf(hh[s], wzv[j], acc[s][4 + j]);
                        acc[s][8 + j] = fmaf(hh[s], wnv[j], acc[s][8 + j]);
                    }
                }
            }
        }
        __syncthreads();   // all GEMM reads of h0s done before epilogue writes

        // ---- layer-0 gate epilogue (in-register) ----
        #pragma unroll
        for (int s = 0; s < 4; s++) {
            const int seq = s0 + s;
            const float x0v = xs[(t * Dd + 0) * SEQ + seq];
            const float x1v = xs[(t * Dd + 1) * SEQ + seq];
            #pragma unroll
            for (int j = 0; j < 4; j++) {
                const int g = g0 + j;
                float gir = fmaf(x1v, wx0s[G3 + g],       fmaf(x0v, wx0s[g],       vbx0[g]));
                float giz = fmaf(x1v, wx0s[G3 + 128 + g], fmaf(x0v, wx0s[128 + g], vbx0[128 + g]));
                float gin = fmaf(x1v, wx0s[G3 + 256 + g], fmaf(x0v, wx0s[256 + g], vbx0[256 + g]));
                float r  = sigm_f(acc[s][j]     + vbh0[g]       + gir);
                float z  = sigm_f(acc[s][4 + j] + vbh0[128 + g] + giz);
                float hn = acc[s][8 + j] + vbh0[256 + g];
                float nn = tanh_f(gin + r * hn);
                float ho = h0s[g * HT + seq];
                h0s[g * HT + seq] = (1.0f - z) * nn + z * ho;
            }
        }
        __syncthreads();   // new h0 visible to layer-1 GEMM

        // ================= layer 1 =================
        // slots: [0..3]=r, [4..7]=z, [8..11]=i_n (x-path), [12..15]=h_n (h-path)
        float a1[4][16];
        #pragma unroll
        for (int s = 0; s < 4; s++)
            #pragma unroll
            for (int j = 0; j < 16; j++) a1[s][j] = 0.0f;

        // x-path: h0_new @ Wx1
        #pragma unroll 1
        for (int kc = 0; kc < 4; kc++) {
            __syncthreads();
            {
                const float4* src = reinterpret_cast<const float4*>(Wx1 + kc * 32 * G3);
                float4* dst = reinterpret_cast<float4*>(Ws);
                #pragma unroll
                for (int i = 0; i < (32 * G3 / 4) / THREADS; i++)
                    dst[tid + i * THREADS] = src[tid + i * THREADS];
            }
            __syncthreads();
            #pragma unroll 4
            for (int kk = 0; kk < 32; kk++) {
                const int k = kc * 32 + kk;
                float4 hv = *reinterpret_cast<const float4*>(&h0s[k * HT + s0]);
                float4 wr = *reinterpret_cast<const float4*>(&Ws[kk * G3 + g0]);
                float4 wz = *reinterpret_cast<const float4*>(&Ws[kk * G3 + 128 + g0]);
                float4 wn = *reinterpret_cast<const float4*>(&Ws[kk * G3 + 256 + g0]);
                const float hh[4]  = {hv.x, hv.y, hv.z, hv.w};
                const float wrv[4] = {wr.x, wr.y, wr.z, wr.w};
                const float wzv[4] = {wz.x, wz.y, wz.z, wz.w};
                const float wnv[4] = {wn.x, wn.y, wn.z, wn.w};
                #pragma unroll
                for (int s = 0; s < 4; s++) {
                    #pragma unroll
                    for (int j = 0; j < 4; j++) {
                        a1[s][j]      = fmaf(hh[s], wrv[j], a1[s][j]);
                        a1[s][4 + j]  = fmaf(hh[s], wzv[j], a1[s][4 + j]);
                        a1[s][8 + j]  = fmaf(hh[s], wnv[j], a1[s][8 + j]);
                    }
                }
            }
        }
        // h-path: h1 @ Wh1
        #pragma unroll 1
        for (int kc = 0; kc < 4; kc++) {
            __syncthreads();
            {
                const float4* src = reinterpret_cast<const float4*>(Wh1 + kc * 32 * G3);
                float4* dst = reinterpret_cast<float4*>(Ws);
                #pragma unroll
                for (int i = 0; i < (32 * G3 / 4) / THREADS; i++)
                    dst[tid + i * THREADS] = src[tid + i * THREADS];
            }
            __syncthreads();
            #pragma unroll 4
            for (int kk = 0; kk < 32; kk++) {
                const int k = kc * 32 + kk;
                float4 hv = *reinterpret_cast<const float4*>(&h1s[k * HT + s0]);
                float4 wr = *reinterpret_cast<const float4*>(&Ws[kk * G3 + g0]);
                float4 wz = *reinterpret_cast<const float4*>(&Ws[kk * G3 + 128 + g0]);
                float4 wn = *reinterpret_cast<const float4*>(&Ws[kk * G3 + 256 + g0]);
                const float hh[4]  = {hv.x, hv.y, hv.z, hv.w};
                const float wrv[4] = {wr.x, wr.y, wr.z, wr.w};
                const float wzv[4] = {wz.x, wz.y, wz.z, wz.w};
                const float wnv[4] = {wn.x, wn.y, wn.z, wn.w};
                #pragma unroll
                for (int s = 0; s < 4; s++) {
                    #pragma unroll
                    for (int j = 0; j < 4; j++) {
                        a1[s][j]      = fmaf(hh[s], wrv[j], a1[s][j]);
                        a1[s][4 + j]  = fmaf(hh[s], wzv[j], a1[s][4 + j]);
                        a1[s][12 + j] = fmaf(hh[s], wnv[j], a1[s][12 + j]);
                    }
                }
            }
        }
        __syncthreads();   // all GEMM reads of h1s done before epilogue writes

        // ---- layer-1 gate epilogue ----
        #pragma unroll
        for (int s = 0; s < 4; s++) {
            const int seq = s0 + s;
            #pragma unroll
            for (int j = 0; j < 4; j++) {
                const int g = g0 + j;
                float r   = sigm_f(a1[s][j]     + vbx1[g]       + vbh1[g]);
                float z   = sigm_f(a1[s][4 + j] + vbx1[128 + g] + vbh1[128 + g]);
                float in_ = a1[s][8 + j]  + vbx1[256 + g];
                float hn  = a1[s][12 + j] + vbh1[256 + g];
                float nn  = tanh_f(in_ + r * hn);
                float ho  = h1s[g * HT + seq];
                h1s[g * HT + seq] = (1.0f - z) * nn + z * ho;
            }
        }
        __syncthreads();
    }

    // ---- write final hidden states: out[2][B][H][N] ----
    for (int i = tid; i < 2 * Hh * SEQ; i += THREADS) {
        int l   = i >> 13;          // / (H*SEQ) = 8192
        int rem = i & 8191;
        int g   = rem >> 6;
        int s   = rem & 63;
        float v = (l ? h1s : h0s)[g * HT + s];
        out[((l * Bb + b) * Hh + g) * Nn + n0 + s] = v;
    }
}

extern "C" void kernel_launch(void* const* d_in, const int* in_sizes, int n_in,
                              void* d_out, int out_size) {
    (void)in_sizes; (void)n_in; (void)out_size;
    const float* x   = (const float*)d_in[0];
    const float* Wx0 = (const float*)d_in[1];
    const float* Wh0 = (const float*)d_in[2];
    const float* bx0 = (const float*)d_in[3];
    const float* bh0 = (const float*)d_in[4];
    const float* Wx1 = (const float*)d_in[5];
    const float* Wh1 = (const float*)d_in[6];
    const float* bx1 = (const float*)d_in[7];
    const float* bh1 = (const float*)d_in[8];
    float* out = (float*)d_out;

    const size_t smem_bytes = SMEM_FLOATS * sizeof(float);  // 140288
    cudaFuncSetAttribute(gru_fused_kernel,
                         cudaFuncAttributeMaxDynamicSharedMemorySize,
                         (int)smem_bytes);

    gru_fused_kernel<<<CTAS, THREADS, smem_bytes>>>(
        x, Wx0, Wh0, bx0, bh0, Wx1, Wh1, bx1, bh1, out);
}